// round 6
// baseline (speedup 1.0000x reference)
#include <cuda_runtime.h>
#include <cstdint>

// Problem constants: N=4096, L_V=64, H=512, D=256
constexpr int NB   = 4096;
constexpr int LV   = 64;
constexpr int HD   = 512;
constexpr int DD   = 256;
constexpr int K1   = 3 * DD;   // 768
constexpr int KTOT = K1 + HD;  // 1280

// GEMM tiling
constexpr int BM = 128, BN = 128, BK = 16;
constexpr int TM = 8,   TN = 8;
constexpr int NIT  = KTOT / BK;  // 80
constexpr int ASTR = 16;
constexpr int GEMM_CTAS  = (NB / BM) * (HD / BN);  // 128
constexpr int TOTAL_CTAS = 304;                    // 2 per SM on 152 SMs

// Bulk copy: 16KB chunks over the 512MB passthrough
constexpr int      CHUNK   = 16384;
constexpr long long TOTAL_BYTES = (long long)NB * LV * HD * 4;  // 512MB
constexpr int      NCHUNKS = (int)(TOTAL_BYTES / CHUNK);        // 32768

// Shared scratch: GEMM tiles or copy double-buffer (union via raw bytes)
constexpr int SMEM_BYTES = 2 * CHUNK + 1024;   // 33KB < 48KB static limit

__device__ int   g_copy_ctr;
__device__ float g_stage[NB * HD];             // dense next_h staging (8MB)

__global__ void reset_kernel() { g_copy_ctr = 0; }

// ---------------- PTX helpers ----------------
__device__ __forceinline__ uint32_t s2u(const void* p) {
    uint32_t a;
    asm("{ .reg .u64 t; cvta.to.shared.u64 t, %1; cvt.u32.u64 %0, t; }"
        : "=r"(a) : "l"(p));
    return a;
}
__device__ __forceinline__ void cp16(uint32_t dst, const void* src) {
    asm volatile("cp.async.cg.shared.global [%0], [%1], 16;" :: "r"(dst), "l"(src));
}
__device__ __forceinline__ void cp_commit() {
    asm volatile("cp.async.commit_group;");
}
template <int N>
__device__ __forceinline__ void cp_wait() {
    asm volatile("cp.async.wait_group %0;" :: "n"(N));
}
__device__ __forceinline__ unsigned long long dup2(float v) {
    unsigned long long r;
    asm("mov.b64 %0, {%1, %1};" : "=l"(r) : "f"(v));
    return r;
}
__device__ __forceinline__ void ffma2(unsigned long long& d,
                                      unsigned long long a,
                                      unsigned long long b) {
    asm("fma.rn.f32x2 %0, %1, %2, %0;" : "+l"(d) : "l"(a), "l"(b));
}
__device__ __forceinline__ void unpack2(unsigned long long v, float& lo, float& hi) {
    asm("mov.b64 {%0, %1}, %2;" : "=f"(lo), "=f"(hi) : "l"(v));
}
// ---- bulk-async (TMA) 1D helpers ----
__device__ __forceinline__ void mbar_init(uint32_t mbar, uint32_t cnt) {
    asm volatile("mbarrier.init.shared.b64 [%0], %1;" :: "r"(mbar), "r"(cnt) : "memory");
}
__device__ __forceinline__ void mbar_expect(uint32_t mbar, uint32_t bytes) {
    asm volatile("mbarrier.arrive.expect_tx.shared.b64 _, [%0], %1;"
                 :: "r"(mbar), "r"(bytes) : "memory");
}
__device__ __forceinline__ void mbar_wait(uint32_t mbar, uint32_t parity) {
    asm volatile(
        "{\n\t.reg .pred P;\n\t"
        "WAIT_%=:\n\t"
        "mbarrier.try_wait.parity.acquire.cta.shared::cta.b64 P, [%0], %1, 0x989680;\n\t"
        "@P bra.uni DONE_%=;\n\t"
        "bra.uni WAIT_%=;\n\t"
        "DONE_%=:\n\t}"
        :: "r"(mbar), "r"(parity) : "memory");
}
__device__ __forceinline__ void bulk_load(uint32_t dst, const void* src,
                                          uint32_t bytes, uint32_t mbar) {
    asm volatile(
        "cp.async.bulk.shared::cluster.global.mbarrier::complete_tx::bytes "
        "[%0], [%1], %2, [%3];"
        :: "r"(dst), "l"(src), "r"(bytes), "r"(mbar) : "memory");
}
__device__ __forceinline__ void bulk_store(void* dst, uint32_t src, uint32_t bytes) {
    asm volatile("cp.async.bulk.global.shared::cta.bulk_group [%0], [%1], %2;"
                 :: "l"(dst), "r"(src), "r"(bytes) : "memory");
}
__device__ __forceinline__ void bulk_commit() {
    asm volatile("cp.async.bulk.commit_group;");
}
template <int N>
__device__ __forceinline__ void bulk_wait_read() {
    asm volatile("cp.async.bulk.wait_group.read %0;" :: "n"(N) : "memory");
}
template <int N>
__device__ __forceinline__ void bulk_wait() {
    asm volatile("cp.async.bulk.wait_group %0;" :: "n"(N) : "memory");
}
__device__ __forceinline__ void fence_async_shared() {
    asm volatile("fence.proxy.async.shared::cta;" ::: "memory");
}

// --------------------------------------------------------------------------
// Copy role (single thread per CTA): work-stealing bulk-async passthrough.
// Double-buffered 16KB chunks: gmem -> smem (mbarrier) -> gmem (bulk_group).
// Copies ALL rows (scatter rows fixed up by the scatter kernel afterwards).
// --------------------------------------------------------------------------
__device__ void copy_role_tma(char* raw, const char* __restrict__ src,
                              char* __restrict__ dst)
{
    const uint32_t b[2]  = { s2u(raw), s2u(raw + CHUNK) };
    const uint32_t mb[2] = { s2u(raw + 2 * CHUNK), s2u(raw + 2 * CHUNK) + 8 };
    mbar_init(mb[0], 1);
    mbar_init(mb[1], 1);
    fence_async_shared();
    int ph[2] = {0, 0};

    int c = atomicAdd(&g_copy_ctr, 1);
    if (c >= NCHUNKS) return;
    mbar_expect(mb[0], CHUNK);
    bulk_load(b[0], src + (size_t)c * CHUNK, CHUNK, mb[0]);

    int prevc = c, prevbuf = 0;
    for (;;) {
        int  nc    = atomicAdd(&g_copy_ctr, 1);
        bool nhave = nc < NCHUNKS;
        if (nhave) {
            int nbuf = prevbuf ^ 1;
            bulk_wait_read<1>();             // nbuf's previous store has read smem
            mbar_expect(mb[nbuf], CHUNK);
            bulk_load(b[nbuf], src + (size_t)nc * CHUNK, CHUNK, mb[nbuf]);
        }
        mbar_wait(mb[prevbuf], ph[prevbuf]); // prev chunk landed in smem
        ph[prevbuf] ^= 1;
        bulk_store(dst + (size_t)prevc * CHUNK, b[prevbuf], CHUNK);
        bulk_commit();
        if (!nhave) break;
        prevc   = nc;
        prevbuf ^= 1;
    }
    bulk_wait<0>();                          // all stores complete before exit
}

// --------------------------------------------------------------------------
// Fused kernel. bids [0,128): one 128x128 tile of
//   tanh(X@W_in + cur_h@W_h + b) written DENSELY to g_stage[n, :]
// (cp.async double-buffered mainloop, FFMA2 math). Afterwards — and for all
// other bids from the start — thread 0 joins the bulk-copy pool.
// --------------------------------------------------------------------------
__global__ __launch_bounds__(256, 2)
void fused_kernel(const float* __restrict__ memory,
                  const int*   __restrict__ veh_idx,
                  const float* __restrict__ veh_repr,
                  const float* __restrict__ cust_repr,
                  const float* __restrict__ edge_emb,
                  const float* __restrict__ W_in,
                  const float* __restrict__ b_in,
                  const float* __restrict__ W_h,
                  const float* __restrict__ b_h,
                  float* __restrict__ out)
{
    __shared__ __align__(128) char raw[SMEM_BYTES];

    const int tid = threadIdx.x;
    const int bid = blockIdx.x;

    if (bid < GEMM_CTAS) {
        // GEMM view of the shared scratch
        float (*As2)[BM][ASTR] = (float (*)[BM][ASTR])(raw);               // 16KB
        float (*Bs)[BK][BN]    = (float (*)[BK][BN])(raw + BM * BK * 8);   // 16KB
        int*   idx_s           = (int*)(raw + 2 * BM * BK * 8);            // 512B

        const int block_m = (bid >> 2) * BM;
        const int block_n = (bid & 3) * BN;

        if (tid < BM) idx_s[tid] = veh_idx[block_m + tid] & (LV - 1);
        __syncthreads();

        // A cp.async mapping: 512 16B-chunks = 128 m x 4 k-chunks; 2/thread
        const int m0  = tid >> 2;
        const int kc  = (tid & 3) * 4;
        const int gm0 = block_m + m0;
        const int gm1 = gm0 + 64;
        const size_t memrow0 = ((size_t)gm0 * LV + idx_s[m0])      * HD;
        const size_t memrow1 = ((size_t)gm1 * LV + idx_s[m0 + 64]) * HD;
        const uint32_t aDst0 = s2u(&As2[0][m0][kc]);
        const uint32_t aDst1 = s2u(&As2[0][m0 + 64][kc]);

        // B cp.async mapping: 512 chunks = 16 k x 32 n-chunks; 2/thread
        const int kb = tid >> 5;
        const int nc = (tid & 31) * 4;
        const uint32_t bDst0 = s2u(&Bs[0][kb][nc]);
        const uint32_t bDst1 = s2u(&Bs[0][kb + 8][nc]);

        auto issue_tile = [&](int it, int buf) {
            const int k0 = it * BK;
            const uint32_t aoff = buf ? (uint32_t)(BM * ASTR * 4) : 0u;
            const uint32_t boff = buf ? (uint32_t)(BK * BN * 4)   : 0u;
            const float *s0, *s1;
            if (k0 < DD) {
                s0 = veh_repr + (size_t)gm0 * DD + k0 + kc;
                s1 = veh_repr + (size_t)gm1 * DD + k0 + kc;
            } else if (k0 < 2 * DD) {
                const int o = k0 - DD;
                s0 = cust_repr + (size_t)gm0 * DD + o + kc;
                s1 = cust_repr + (size_t)gm1 * DD + o + kc;
            } else if (k0 < K1) {
                const int o = k0 - 2 * DD;
                s0 = edge_emb + (size_t)gm0 * DD + o + kc;
                s1 = edge_emb + (size_t)gm1 * DD + o + kc;
            } else {
                const int o = k0 - K1;
                s0 = memory + memrow0 + o + kc;
                s1 = memory + memrow1 + o + kc;
            }
            cp16(aDst0 + aoff, s0);
            cp16(aDst1 + aoff, s1);

            const int gk0 = k0 + kb;
            const int gk1 = gk0 + 8;
            const float* w0 = (gk0 < K1) ? (W_in + (size_t)gk0 * HD)
                                         : (W_h + (size_t)(gk0 - K1) * HD);
            const float* w1 = (gk1 < K1) ? (W_in + (size_t)gk1 * HD)
                                         : (W_h + (size_t)(gk1 - K1) * HD);
            cp16(bDst0 + boff, w0 + block_n + nc);
            cp16(bDst1 + boff, w1 + block_n + nc);
            cp_commit();
        };

        const int tm = (tid >> 4) * TM;
        const int tn = (tid & 15) * TN;

        unsigned long long acc[TM][TN / 2];
        #pragma unroll
        for (int i = 0; i < TM; i++)
            #pragma unroll
            for (int j = 0; j < TN / 2; j++) acc[i][j] = 0ull;

        issue_tile(0, 0);

        for (int it = 0; it < NIT; it++) {
            const int buf = it & 1;
            if (it + 1 < NIT) {
                issue_tile(it + 1, buf ^ 1);
                cp_wait<1>();
            } else {
                cp_wait<0>();
            }
            __syncthreads();

            #pragma unroll
            for (int k2 = 0; k2 < BK / 2; k2++) {
                float2 a01[TM];
                #pragma unroll
                for (int i = 0; i < TM; i++)
                    a01[i] = *(const float2*)&As2[buf][tm + i][2 * k2];

                ulonglong2 B00 = *(const ulonglong2*)&Bs[buf][2 * k2][tn];
                ulonglong2 B01 = *(const ulonglong2*)&Bs[buf][2 * k2][tn + 4];
                ulonglong2 B10 = *(const ulonglong2*)&Bs[buf][2 * k2 + 1][tn];
                ulonglong2 B11 = *(const ulonglong2*)&Bs[buf][2 * k2 + 1][tn + 4];
                unsigned long long b0[4] = {B00.x, B00.y, B01.x, B01.y};
                unsigned long long b1[4] = {B10.x, B10.y, B11.x, B11.y};

                #pragma unroll
                for (int i = 0; i < TM; i++) {
                    const unsigned long long a0 = dup2(a01[i].x);
                    const unsigned long long a1 = dup2(a01[i].y);
                    #pragma unroll
                    for (int j = 0; j < 4; j++) {
                        ffma2(acc[i][j], a0, b0[j]);
                        ffma2(acc[i][j], a1, b1[j]);
                    }
                }
            }
            __syncthreads();
        }

        // epilogue: unpack + bias + tanh -> DENSE staging (no scatter here)
        float bias[TN];
        #pragma unroll
        for (int j = 0; j < TN; j++) {
            const int n = block_n + tn + j;
            bias[j] = b_in[n] + b_h[n];
        }
        #pragma unroll
        for (int i = 0; i < TM; i++) {
            const int gm = block_m + tm + i;
            float* dst = &g_stage[(size_t)gm * HD + block_n + tn];
            float o[TN];
            #pragma unroll
            for (int j = 0; j < 4; j++)
                unpack2(acc[i][j], o[2 * j], o[2 * j + 1]);
            float4 o0, o1;
            o0.x = tanhf(o[0] + bias[0]);
            o0.y = tanhf(o[1] + bias[1]);
            o0.z = tanhf(o[2] + bias[2]);
            o0.w = tanhf(o[3] + bias[3]);
            o1.x = tanhf(o[4] + bias[4]);
            o1.y = tanhf(o[5] + bias[5]);
            o1.z = tanhf(o[6] + bias[6]);
            o1.w = tanhf(o[7] + bias[7]);
            *(float4*)&dst[0] = o0;
            *(float4*)&dst[4] = o1;
        }
        // smem tiles are dead past the last __syncthreads inside the loop;
        // thread 0 can repurpose them for the copy pool.
    }

    if (tid != 0) return;   // copy role is single-threaded per CTA
    copy_role_tma(raw, (const char*)memory, (char*)out);
}

// --------------------------------------------------------------------------
// Scatter kernel: out[n, veh_idx[n], :] = g_stage[n, :]  (runs after fused)
// --------------------------------------------------------------------------
__global__ __launch_bounds__(128)
void scatter_kernel(const int* __restrict__ veh_idx, float* __restrict__ out)
{
    const int n   = blockIdx.x;
    const int idx = veh_idx[n] & (LV - 1);
    const float4* s = (const float4*)&g_stage[(size_t)n * HD];
    float4*       d = (float4*)&out[((size_t)n * LV + idx) * HD];
    d[threadIdx.x] = s[threadIdx.x];
}

extern "C" void kernel_launch(void* const* d_in, const int* in_sizes, int n_in,
                              void* d_out, int out_size)
{
    const float* memory    = (const float*)d_in[0];
    const int*   veh_idx   = (const int*)d_in[1];
    const float* veh_repr  = (const float*)d_in[2];
    const float* cust_repr = (const float*)d_in[3];
    const float* edge_emb  = (const float*)d_in[4];
    const float* W_in      = (const float*)d_in[5];
    const float* b_in      = (const float*)d_in[6];
    const float* W_h       = (const float*)d_in[7];
    const float* b_h       = (const float*)d_in[8];
    float*       out       = (float*)d_out;

    reset_kernel<<<1, 1>>>();
    fused_kernel<<<TOTAL_CTAS, 256>>>(memory, veh_idx, veh_repr, cust_repr,
                                      edge_emb, W_in, b_in, W_h, b_h, out);
    scatter_kernel<<<NB, 128>>>(veh_idx, out);
}

// round 7
// speedup vs baseline: 1.0472x; 1.0472x over previous
#include <cuda_runtime.h>
#include <cstdint>

// Problem constants: N=4096, L_V=64, H=512, D=256
constexpr int NB   = 4096;
constexpr int LV   = 64;
constexpr int HD   = 512;
constexpr int DD   = 256;
constexpr int K1   = 3 * DD;   // 768
constexpr int KTOT = K1 + HD;  // 1280

// GEMM tiling
constexpr int BM = 128, BN = 128, BK = 16;
constexpr int TM = 8,   TN = 8;
constexpr int NIT    = KTOT / BK;  // 80
constexpr int NSTAGE = 3;          // 3-stage cp.async pipeline, 48KB smem
constexpr int GEMM_CTAS  = (NB / BM) * (HD / BN);  // 128
constexpr int TOTAL_CTAS = 304;                    // 2 per SM on 152 SMs

// Copy pool
constexpr int ROWS_TOTAL = NB * LV;                // 262144 rows of 512 floats
constexpr int NUM_GRABS  = ROWS_TOTAL / 32;        // 8192, 32 rows per grab

__device__ int   g_copy_ctr;                       // zero-init at load
__device__ float g_stage[NB * HD];                 // dense next_h staging (8MB)

// ---------------- PTX helpers ----------------
__device__ __forceinline__ uint32_t s2u(const void* p) {
    uint32_t a;
    asm("{ .reg .u64 t; cvta.to.shared.u64 t, %1; cvt.u32.u64 %0, t; }"
        : "=r"(a) : "l"(p));
    return a;
}
__device__ __forceinline__ void cp16(uint32_t dst, const void* src) {
    asm volatile("cp.async.cg.shared.global [%0], [%1], 16;" :: "r"(dst), "l"(src));
}
__device__ __forceinline__ void cp_commit() {
    asm volatile("cp.async.commit_group;");
}
template <int N>
__device__ __forceinline__ void cp_wait() {
    asm volatile("cp.async.wait_group %0;" :: "n"(N));
}
__device__ __forceinline__ unsigned long long dup2(float v) {
    unsigned long long r;
    asm("mov.b64 %0, {%1, %1};" : "=l"(r) : "f"(v));
    return r;
}
__device__ __forceinline__ void ffma2(unsigned long long& d,
                                      unsigned long long a,
                                      unsigned long long b) {
    asm("fma.rn.f32x2 %0, %1, %2, %0;" : "+l"(d) : "l"(a), "l"(b));
}
__device__ __forceinline__ void unpack2(unsigned long long v, float& lo, float& hi) {
    asm("mov.b64 {%0, %1}, %2;" : "=f"(lo), "=f"(hi) : "l"(v));
}
// evict-first (streaming) global ld/st — keeps the 1GB copy stream from
// evicting the hot GEMM weights out of L2
__device__ __forceinline__ float4 ldcs(const float4* p) {
    float4 v;
    asm volatile("ld.global.cs.v4.f32 {%0,%1,%2,%3}, [%4];"
                 : "=f"(v.x), "=f"(v.y), "=f"(v.z), "=f"(v.w) : "l"(p));
    return v;
}
__device__ __forceinline__ void stcs(float4* p, float4 v) {
    asm volatile("st.global.cs.v4.f32 [%0], {%1,%2,%3,%4};"
                 :: "l"(p), "f"(v.x), "f"(v.y), "f"(v.z), "f"(v.w) : "memory");
}

// --------------------------------------------------------------------------
// Copy role: work-stealing passthrough. Warp grabs 32 rows; 4 rows per group
// (16 LDG.128 in flight), stores skip the row the GEMM scatters. .cs hints.
// --------------------------------------------------------------------------
__device__ __forceinline__ void copy_role(const float4* __restrict__ src,
                                          float4* __restrict__ dst,
                                          const int* __restrict__ veh_idx,
                                          int lane)
{
    for (;;) {
        int c;
        if (lane == 0) c = atomicAdd(&g_copy_ctr, 1);
        c = __shfl_sync(0xffffffffu, c, 0);
        if (c >= NUM_GRABS) return;

        const int r0   = c * 32;            // multiple of 32 -> same n whole grab
        const int n    = r0 >> 6;
        const int skip = veh_idx[n] & (LV - 1);
        const int l0   = r0 & 63;           // 0 or 32

        for (int g = 0; g < 8; g++) {       // 8 groups of 4 rows
            float4 v[16];
            size_t base = (size_t)(r0 + g * 4) * (HD / 4) + lane;
            #pragma unroll
            for (int rr = 0; rr < 4; rr++)
                #pragma unroll
                for (int q = 0; q < 4; q++)
                    v[rr * 4 + q] = ldcs(src + base + rr * 128 + q * 32);
            #pragma unroll
            for (int rr = 0; rr < 4; rr++) {
                if (l0 + g * 4 + rr == skip) continue;   // GEMM owns this row
                #pragma unroll
                for (int q = 0; q < 4; q++)
                    stcs(dst + base + rr * 128 + q * 32, v[rr * 4 + q]);
            }
        }
    }
}

// --------------------------------------------------------------------------
// Fused kernel. bids [0,128): one 128x128 tile of
//   tanh(X@W_in + cur_h@W_h + b) written DENSELY to g_stage (scatter kernel
// places it afterwards). 3-stage cp.async pipeline, FFMA2 math, 1 bar/tile.
// All CTAs end in (copy-only CTAs start in) the copy pool.
// --------------------------------------------------------------------------
__global__ __launch_bounds__(256, 2)
void fused_kernel(const float* __restrict__ memory,
                  const int*   __restrict__ veh_idx,
                  const float* __restrict__ veh_repr,
                  const float* __restrict__ cust_repr,
                  const float* __restrict__ edge_emb,
                  const float* __restrict__ W_in,
                  const float* __restrict__ b_in,
                  const float* __restrict__ W_h,
                  const float* __restrict__ b_h,
                  float* __restrict__ out)
{
    __shared__ float As2[NSTAGE][BM][BK];   // 3 x 8KB
    __shared__ float Bs[NSTAGE][BK][BN];    // 3 x 8KB   (total 48KB exactly)

    const int tid  = threadIdx.x;
    const int bid  = blockIdx.x;
    const int lane = tid & 31;

    if (bid < GEMM_CTAS) {
        const int block_m = (bid >> 2) * BM;
        const int block_n = (bid & 3) * BN;

        // A cp.async mapping: 512 16B-chunks = 128 m x 4 k-chunks; 2/thread
        const int m0  = tid >> 2;
        const int kc  = (tid & 3) * 4;
        const int gm0 = block_m + m0;
        const int gm1 = gm0 + 64;
        const int idx0 = veh_idx[gm0] & (LV - 1);
        const int idx1 = veh_idx[gm1] & (LV - 1);
        const size_t memrow0 = ((size_t)gm0 * LV + idx0) * HD;
        const size_t memrow1 = ((size_t)gm1 * LV + idx1) * HD;
        const uint32_t aDst0 = s2u(&As2[0][m0][kc]);
        const uint32_t aDst1 = s2u(&As2[0][m0 + 64][kc]);

        // B cp.async mapping: 512 chunks = 16 k x 32 n-chunks; 2/thread
        const int kb = tid >> 5;
        const int nc = (tid & 31) * 4;
        const uint32_t bDst0 = s2u(&Bs[0][kb][nc]);
        const uint32_t bDst1 = s2u(&Bs[0][kb + 8][nc]);

        constexpr uint32_t A_STAGE = BM * BK * 4;   // 8192
        constexpr uint32_t B_STAGE = BK * BN * 4;   // 8192

        auto issue_tile = [&](int it, int buf) {
            const int k0 = it * BK;
            const uint32_t aoff = (uint32_t)buf * A_STAGE;
            const uint32_t boff = (uint32_t)buf * B_STAGE;
            const float *s0, *s1;
            if (k0 < DD) {
                s0 = veh_repr + (size_t)gm0 * DD + k0 + kc;
                s1 = veh_repr + (size_t)gm1 * DD + k0 + kc;
            } else if (k0 < 2 * DD) {
                const int o = k0 - DD;
                s0 = cust_repr + (size_t)gm0 * DD + o + kc;
                s1 = cust_repr + (size_t)gm1 * DD + o + kc;
            } else if (k0 < K1) {
                const int o = k0 - 2 * DD;
                s0 = edge_emb + (size_t)gm0 * DD + o + kc;
                s1 = edge_emb + (size_t)gm1 * DD + o + kc;
            } else {
                const int o = k0 - K1;
                s0 = memory + memrow0 + o + kc;
                s1 = memory + memrow1 + o + kc;
            }
            cp16(aDst0 + aoff, s0);
            cp16(aDst1 + aoff, s1);

            const int gk0 = k0 + kb;
            const int gk1 = gk0 + 8;
            const float* w0 = (gk0 < K1) ? (W_in + (size_t)gk0 * HD)
                                         : (W_h + (size_t)(gk0 - K1) * HD);
            const float* w1 = (gk1 < K1) ? (W_in + (size_t)gk1 * HD)
                                         : (W_h + (size_t)(gk1 - K1) * HD);
            cp16(bDst0 + boff, w0 + block_n + nc);
            cp16(bDst1 + boff, w1 + block_n + nc);
            cp_commit();
        };

        const int tm = (tid >> 4) * TM;
        const int tn = (tid & 15) * TN;

        unsigned long long acc[TM][TN / 2];
        #pragma unroll
        for (int i = 0; i < TM; i++)
            #pragma unroll
            for (int j = 0; j < TN / 2; j++) acc[i][j] = 0ull;

        issue_tile(0, 0);
        issue_tile(1, 1);

        int buf = 0, nbuf = 2;   // nbuf = (it+2) % 3
        for (int it = 0; it < NIT; it++) {
            if (it + 2 < NIT) cp_wait<1>(); else cp_wait<0>();
            __syncthreads();     // tile 'it' visible CTA-wide; readers of
                                 // tile it-1 all done -> safe to overwrite
            if (it + 2 < NIT) issue_tile(it + 2, nbuf);

            #pragma unroll
            for (int k2 = 0; k2 < BK / 2; k2++) {
                float2 a01[TM];
                #pragma unroll
                for (int i = 0; i < TM; i++)
                    a01[i] = *(const float2*)&As2[buf][tm + i][2 * k2];

                ulonglong2 B00 = *(const ulonglong2*)&Bs[buf][2 * k2][tn];
                ulonglong2 B01 = *(const ulonglong2*)&Bs[buf][2 * k2][tn + 4];
                ulonglong2 B10 = *(const ulonglong2*)&Bs[buf][2 * k2 + 1][tn];
                ulonglong2 B11 = *(const ulonglong2*)&Bs[buf][2 * k2 + 1][tn + 4];
                unsigned long long b0[4] = {B00.x, B00.y, B01.x, B01.y};
                unsigned long long b1[4] = {B10.x, B10.y, B11.x, B11.y};

                #pragma unroll
                for (int i = 0; i < TM; i++) {
                    const unsigned long long a0 = dup2(a01[i].x);
                    const unsigned long long a1 = dup2(a01[i].y);
                    #pragma unroll
                    for (int j = 0; j < 4; j++) {
                        ffma2(acc[i][j], a0, b0[j]);
                        ffma2(acc[i][j], a1, b1[j]);
                    }
                }
            }
            buf  = (buf  == 2) ? 0 : buf + 1;
            nbuf = (nbuf == 2) ? 0 : nbuf + 1;
        }

        // epilogue: unpack + bias + tanh -> DENSE staging (no scatter here)
        float bias[TN];
        #pragma unroll
        for (int j = 0; j < TN; j++) {
            const int n = block_n + tn + j;
            bias[j] = b_in[n] + b_h[n];
        }
        #pragma unroll
        for (int i = 0; i < TM; i++) {
            const int gm = block_m + tm + i;
            float* dst = &g_stage[(size_t)gm * HD + block_n + tn];
            float o[TN];
            #pragma unroll
            for (int j = 0; j < 4; j++)
                unpack2(acc[i][j], o[2 * j], o[2 * j + 1]);
            float4 o0, o1;
            o0.x = tanhf(o[0] + bias[0]);
            o0.y = tanhf(o[1] + bias[1]);
            o0.z = tanhf(o[2] + bias[2]);
            o0.w = tanhf(o[3] + bias[3]);
            o1.x = tanhf(o[4] + bias[4]);
            o1.y = tanhf(o[5] + bias[5]);
            o1.z = tanhf(o[6] + bias[6]);
            o1.w = tanhf(o[7] + bias[7]);
            *(float4*)&dst[0] = o0;
            *(float4*)&dst[4] = o1;
        }
    }

    // Copy pool (copy-only CTAs arrive here immediately).
    copy_role((const float4*)memory, (float4*)out, veh_idx, lane);
}

// --------------------------------------------------------------------------
// Scatter kernel: out[n, veh_idx[n], :] = g_stage[n, :]; also resets the
// work-stealing counter for the next graph replay.
// --------------------------------------------------------------------------
__global__ __launch_bounds__(128)
void scatter_kernel(const int* __restrict__ veh_idx, float* __restrict__ out)
{
    if (blockIdx.x == 0 && threadIdx.x == 0) g_copy_ctr = 0;
    const int n   = blockIdx.x;
    const int idx = veh_idx[n] & (LV - 1);
    const float4* s = (const float4*)&g_stage[(size_t)n * HD];
    float4*       d = (float4*)&out[((size_t)n * LV + idx) * HD];
    d[threadIdx.x] = s[threadIdx.x];
}

extern "C" void kernel_launch(void* const* d_in, const int* in_sizes, int n_in,
                              void* d_out, int out_size)
{
    const float* memory    = (const float*)d_in[0];
    const int*   veh_idx   = (const int*)d_in[1];
    const float* veh_repr  = (const float*)d_in[2];
    const float* cust_repr = (const float*)d_in[3];
    const float* edge_emb  = (const float*)d_in[4];
    const float* W_in      = (const float*)d_in[5];
    const float* b_in      = (const float*)d_in[6];
    const float* W_h       = (const float*)d_in[7];
    const float* b_h       = (const float*)d_in[8];
    float*       out       = (float*)d_out;

    fused_kernel<<<TOTAL_CTAS, 256>>>(memory, veh_idx, veh_repr, cust_repr,
                                      edge_emb, W_in, b_in, W_h, b_h, out);
    scatter_kernel<<<NB, 128>>>(veh_idx, out);
}